// round 10
// baseline (speedup 1.0000x reference)
#include <cuda_runtime.h>
#include <cstddef>
#include <math.h>

#define T_ 4
#define B_ 16
#define C_ 256
#define N_ 512
#define H_ 1024
#define BK 8

// ---------------- scratch (device globals; no allocation allowed) ----------
__device__ __align__(16) float g_qs[(size_t)T_*B_*C_*N_];
__device__ __align__(16) float g_ks[(size_t)T_*B_*C_*N_];
__device__ __align__(16) float g_vs[(size_t)T_*B_*C_*N_];
__device__ __align__(16) float g_rs[(size_t)T_*B_*C_*N_];
__device__ __align__(16) float g_x1[(size_t)T_*B_*C_*N_];
__device__ __align__(16) float g_h [(size_t)T_*B_*H_*N_];

__device__ __forceinline__ float* buf_ptr(int id){
  switch(id){
    case 0: return g_qs; case 1: return g_ks; case 2: return g_vs;
    case 3: return g_rs; case 4: return g_x1; default: return g_h;
  }
}

// ---------------- packed f32x2 helpers (bit-exact per-lane IEEE fma) -------
__device__ __forceinline__ unsigned long long pk2(float v){
  unsigned long long r; unsigned u = __float_as_uint(v);
  asm("mov.b64 %0, {%1, %1};" : "=l"(r) : "r"(u));
  return r;
}
__device__ __forceinline__ void fma2(unsigned long long &d,
                                     unsigned long long a, unsigned long long b){
  asm("fma.rn.f32x2 %0, %1, %2, %0;" : "+l"(d) : "l"(a), "l"(b));
}
__device__ __forceinline__ float2 unpk(unsigned long long p){
  unsigned lo, hi;
  asm("mov.b64 {%0, %1}, %2;" : "=r"(lo), "=r"(hi) : "l"(p));
  return make_float2(__uint_as_float(lo), __uint_as_float(hi));
}

// ------------- fused GEMM + (reference-order) BN + LIF scan over T
// All T=4 pre-activations accumulated in one k-pass (t in the register tile);
// per-output accumulation: serial ascending-c fp32 fma; FFMA2 pairs ADJACENT
// O-ROWS (b-operand = duplicated X pair) -> bit-exact vs scalar reference.
// Block tile: 64(o) x 32(n) x 4(t), 128 threads, micro 8(o) x 2(n) x 4(t).
// 3 CTAs/SM (12 warps). Double-buffered smem, register-prefetch pipeline,
// compile-time stage indices (2 tiles per loop iteration).
#define XROW 320   // 16 n-pairs * 20 floats (n-even 8, n-odd 8, pad 4)
__device__ __forceinline__ void gemm_lif_body(
    const float* __restrict__ X, float* __restrict__ out,
    const float* __restrict__ res,
    const float* __restrict__ W, const float* __restrict__ bn,
    const float* __restrict__ bias, int Cin, int Cout,
    int b, int o0, int n0)
{
  __shared__ __align__(16) float sW [2][BK][64];    // [stage][k][o]
  __shared__ __align__(16) float sX2[2][BK][XROW];  // dup pairs [stage][k][col]
  __shared__ float sBN[4][64];                      // s, mean, beta, convbias

  const int tid = threadIdx.x;
  const int to = tid >> 4;          // 0..7  -> o micro group (8 o each)
  const int tn = tid & 15;          // 0..15 -> n pair (2 each)

  // W staging: swo = o row (0..63), swk = k quad (0 or 4); one LDG.128/thread
  const int swo = tid >> 1;
  const int swk = (tid & 1) * 4;
  // X staging: xk = k row, xt = t, xq -> n chunks {xq*4, xq*4+16}
  const int xk = tid >> 4;          // 0..7
  const int xt = (tid >> 2) & 3;    // 0..3
  const int xq = tid & 3;           // 0..3

  if (tid < 64) {
    const int o = o0 + tid;
    sBN[0][tid] = bn[o] / sqrtf(bn[3*Cout + o] + 1e-5f);
    sBN[1][tid] = bn[2*Cout + o];
    sBN[2][tid] = bn[Cout + o];
    sBN[3][tid] = bias ? bias[o] : 0.0f;
  }

  // register prefetch buffers
  float4 rw, rx0, rx1;
  auto load_regs = [&](int kk){
    rw  = *(const float4*)(W + (size_t)(o0 + swo) * Cin + kk + swk);
    const float* xp = X + ((size_t)(xt*B_ + b) * Cin + kk + xk) * N_ + n0;
    rx0 = *(const float4*)(xp + xq*4);
    rx1 = *(const float4*)(xp + xq*4 + 16);
  };
  auto sts_regs = [&](int s){
    sW[s][swk+0][swo] = rw.x; sW[s][swk+1][swo] = rw.y;
    sW[s][swk+2][swo] = rw.z; sW[s][swk+3][swo] = rw.w;
    float xv0[4] = {rx0.x, rx0.y, rx0.z, rx0.w};
    float xv1[4] = {rx1.x, rx1.y, rx1.z, rx1.w};
#pragma unroll
    for (int i=0;i<4;i++){
      const int nl = xq*4 + i;                        // local n 0..15
      const int col = (nl>>1)*20 + (nl&1)*8 + xt*2;
      *(unsigned long long*)&sX2[s][xk][col] = pk2(xv0[i]);
    }
#pragma unroll
    for (int i=0;i<4;i++){
      const int nl = xq*4 + 16 + i;                   // local n 16..31
      const int col = (nl>>1)*20 + (nl&1)*8 + xt*2;
      *(unsigned long long*)&sX2[s][xk][col] = pk2(xv1[i]);
    }
  };

  // accp[p][j]: packed (o = to*8+2p, +1), j = n*4 + t  (n in 0..1, t in 0..3)
  unsigned long long accp[4][8];
#pragma unroll
  for (int i=0;i<4;i++)
#pragma unroll
    for (int j=0;j<8;j++) accp[i][j] = 0ULL;

  auto compute = [&](int s){
#pragma unroll
    for (int k = 0; k < BK; k++){
      ulonglong2 w01 = *(const ulonglong2*)&sW[s][k][to*8];
      ulonglong2 w23 = *(const ulonglong2*)&sW[s][k][to*8 + 4];
      unsigned long long ap[4] = {w01.x, w01.y, w23.x, w23.y};
      const float* bp = &sX2[s][k][tn*20];
      ulonglong2 q0 = *(const ulonglong2*)(bp);      // (n0,t0),(n0,t1)
      ulonglong2 q1 = *(const ulonglong2*)(bp + 4);  // (n0,t2),(n0,t3)
      ulonglong2 q2 = *(const ulonglong2*)(bp + 8);  // (n1,t0),(n1,t1)
      ulonglong2 q3 = *(const ulonglong2*)(bp + 12); // (n1,t2),(n1,t3)
      unsigned long long pb[8] = {q0.x,q0.y,q1.x,q1.y,q2.x,q2.y,q3.x,q3.y};
#pragma unroll
      for (int j=0; j<8; j++){    // j outer: pb[j] reused by 4 consecutive FFMA2
#pragma unroll
        for (int p=0; p<4; p++) fma2(accp[p][j], ap[p], pb[j]);
      }
    }
  };

  const int ntile = Cin / BK;     // even for all layers
  load_regs(0);

#pragma unroll 1
  for (int it = 0; it < ntile; it += 2){
    // ---- stage 0: tile it ----
    sts_regs(0);
    __syncthreads();
    load_regs((it + 1) * BK);     // always valid (ntile even)
    compute(0);
    // ---- stage 1: tile it+1 ----
    sts_regs(1);
    __syncthreads();
    if (it + 2 < ntile) load_regs((it + 2) * BK);
    compute(1);
    // WAR safety: each sts targets the stage whose last readers passed the
    // immediately preceding barrier (single barrier per tile, stages fixed).
  }

  // epilogue: bias -> BN (reference order) -> LIF scan over t -> +residual
#pragma unroll
  for (int p=0; p<4; p++) {
    float accs[2][8];    // [o-lane within pair][j = n*4 + t]
#pragma unroll
    for (int j=0;j<8;j++){
      float2 pr = unpk(accp[p][j]);
      accs[0][j] = pr.x; accs[1][j] = pr.y;
    }
#pragma unroll
    for (int h2=0; h2<2; h2++) {
      const int oloc = to*8 + 2*p + h2;
      const int o = o0 + oloc;
      const float s_  = sBN[0][oloc];
      const float m_  = sBN[1][oloc];
      const float be_ = sBN[2][oloc];
      const float bc_ = sBN[3][oloc];
#pragma unroll
      for (int n=0; n<2; n++) {
        float mem = 0.0f;
        float sp[4];
#pragma unroll
        for (int t=0; t<4; t++) {
          float ypre = accs[h2][n*4 + t] + bc_;            // conv bias (0 if none)
          float y    = fmaf(ypre - m_, s_, be_);           // (y-m)*s + beta
          float m2   = mem + (y - mem) * 0.5f;             // mem + (y-mem)/TAU
          bool fire  = (m2 > 0.5f);                        // spike(mem - 0.5)
          mem = fire ? 0.0f : m2;                          // hard reset
          sp[t] = fire ? 1.0f : 0.0f;
        }
#pragma unroll
        for (int t=0; t<4; t++) {
          const size_t idx = ((size_t)(t*B_ + b) * Cout + o) * N_ + n0 + tn*2 + n;
          float v = sp[t];
          if (res) v += res[idx];
          out[idx] = v;
        }
      }
    }
  }
}

// q,k,v fused: blockIdx.y in [0,12): gemm = gy>>2, o0 = (gy&3)*64
__global__ __launch_bounds__(128, 3)
void qkv_gemm_kernel(const float* __restrict__ x,
                     const float* __restrict__ Wq, const float* __restrict__ bnq,
                     const float* __restrict__ Wk, const float* __restrict__ bnk,
                     const float* __restrict__ Wv, const float* __restrict__ bnv)
{
  const int gy = blockIdx.y;
  const int gemm = gy >> 2;
  const int o0 = (gy & 3) * 64;
  const float* W  = (gemm == 0) ? Wq  : (gemm == 1) ? Wk  : Wv;
  const float* bn = (gemm == 0) ? bnq : (gemm == 1) ? bnk : bnv;
  float* out = buf_ptr(gemm);
  gemm_lif_body(x, out, nullptr, W, bn, nullptr, C_, C_,
                blockIdx.z, o0, blockIdx.x * 32);
}

__global__ __launch_bounds__(128, 3)
void gemm_lif_kernel(const float* __restrict__ Xext, float* __restrict__ outext,
                     const float* __restrict__ resext,
                     int xid, int oid, int rid,
                     const float* __restrict__ W, const float* __restrict__ bn,
                     const float* __restrict__ bias, int Cin, int Cout)
{
  const float* X   = (xid >= 0) ? buf_ptr(xid) : Xext;
  float* out       = (oid >= 0) ? buf_ptr(oid) : outext;
  const float* res = (rid == -2) ? nullptr : ((rid >= 0) ? buf_ptr(rid) : resext);
  gemm_lif_body(X, out, res, W, bn, bias, Cin, Cout,
                blockIdx.z, blockIdx.y * 64, blockIdx.x * 32);
}

// ------------- spiking linear attention + attn-LIF (bit-exact integer math)
// KV[d1][d2] = sum_m k[d1,m]*v[d2,m] via ballot-bitpack + popc (spikes binary)
// r = 0.0625 * q @ KV ; LIF over t (dyadic-exact).
__global__ __launch_bounds__(256)
void attn_lif_kernel()
{
  __shared__ unsigned kb[16][17], vb[16][17];
  __shared__ float sKV[16][17];
  const int b = blockIdx.x;
  const int h = blockIdx.y;
  const int tid = threadIdx.x;
  const int warp = tid >> 5, lane = tid & 31;
  const int d1 = tid >> 4, d2 = tid & 15;

  float mem[2][16];
#pragma unroll
  for (int j=0;j<2;j++)
#pragma unroll
    for (int d=0; d<16; d++) mem[j][d] = 0.0f;

#pragma unroll 1
  for (int t=0; t<T_; t++){
    const size_t base = ((size_t)(t*B_ + b) * C_ + h*16) * N_;
    __syncthreads();   // prior iteration done reading kb/vb/sKV

#pragma unroll 4
    for (int i = 0; i < 32; i++){
      const int idx = warp * 32 + i;          // 0..255
      const int row = idx >> 4, word = idx & 15;
      const size_t off = base + (size_t)row * N_ + word * 32 + lane;
      unsigned uk = __ballot_sync(0xffffffffu, g_ks[off] != 0.0f);
      unsigned uv = __ballot_sync(0xffffffffu, g_vs[off] != 0.0f);
      if (lane == 0){ kb[row][word] = uk; vb[row][word] = uv; }
    }
    __syncthreads();

    {
      int kv = 0;
#pragma unroll
      for (int w=0; w<16; w++) kv += __popc(kb[d1][w] & vb[d2][w]);
      sKV[d1][d2] = (float)kv;
    }
    __syncthreads();

#pragma unroll
    for (int half=0; half<2; half++){
      const int n = tid + half*256;
      float qv[16];
#pragma unroll
      for (int dd=0; dd<16; dd++) qv[dd] = g_qs[base + (size_t)dd*N_ + n];
#pragma unroll
      for (int d=0; d<16; d++){
        float r = 0.0f;
#pragma unroll
        for (int dd=0; dd<16; dd++) r = fmaf(qv[dd], sKV[dd][d], r);
        r *= 0.0625f;
        float m2 = mem[half][d] + (r - mem[half][d]) * 0.5f;
        bool fire = (m2 > 0.5f);
        mem[half][d] = fire ? 0.0f : m2;
        g_rs[base + (size_t)d*N_ + n] = fire ? 1.0f : 0.0f;
      }
    }
  }
}

// --------------------------------------------------------------------------
extern "C" void kernel_launch(void* const* d_in, const int* in_sizes, int n_in,
                              void* d_out, int out_size)
{
  const float* x       = (const float*)d_in[0];
  const float* q_w     = (const float*)d_in[1];
  const float* q_bn    = (const float*)d_in[2];
  const float* k_w     = (const float*)d_in[3];
  const float* k_bn    = (const float*)d_in[4];
  const float* v_w     = (const float*)d_in[5];
  const float* v_bn    = (const float*)d_in[6];
  const float* proj_w  = (const float*)d_in[7];
  const float* proj_bn = (const float*)d_in[8];
  const float* fc1_w   = (const float*)d_in[9];
  const float* fc1_b   = (const float*)d_in[10];
  const float* fc1_bn  = (const float*)d_in[11];
  const float* fc2_w   = (const float*)d_in[12];
  const float* fc2_b   = (const float*)d_in[13];
  const float* fc2_bn  = (const float*)d_in[14];
  float* out = (float*)d_out;

  dim3 blk(128);

  // q, k, v = conv+bn+lif(x) -> binary spikes (one fused launch, t in-register)
  qkv_gemm_kernel<<<dim3(N_/32, 12, B_), blk>>>(x, q_w, q_bn, k_w, k_bn, v_w, v_bn);

  // linear attention (q (kT v)) * 0.0625 + attn-LIF -> g_rs
  attn_lif_kernel<<<dim3(B_, 16), dim3(256)>>>();

  // proj conv+bn+lif, fused residual: x1 = x + spike
  gemm_lif_kernel<<<dim3(N_/32, C_/64, B_), blk>>>(nullptr, nullptr, x, 3, 4, -1,
                                                   proj_w, proj_bn, nullptr, C_, C_);

  // fc1 conv+bn+lif -> g_h (Cout=1024)
  gemm_lif_kernel<<<dim3(N_/32, H_/64, B_), blk>>>(nullptr, nullptr, nullptr, 4, 5, -2,
                                                   fc1_w, fc1_bn, fc1_b, C_, H_);

  // fc2 conv+bn+lif, fused residual: out = x1 + spike (Cin=1024)
  gemm_lif_kernel<<<dim3(N_/32, C_/64, B_), blk>>>(nullptr, out, nullptr, 5, -1, 4,
                                                   fc2_w, fc2_bn, fc2_b, H_, C_);
}

// round 11
// speedup vs baseline: 1.0494x; 1.0494x over previous
#include <cuda_runtime.h>
#include <cstddef>
#include <math.h>

#define T_ 4
#define B_ 16
#define C_ 256
#define N_ 512
#define H_ 1024
#define BK 8

// ---------------- scratch (device globals; no allocation allowed) ----------
__device__ __align__(16) float g_qs[(size_t)T_*B_*C_*N_];
__device__ __align__(16) float g_ks[(size_t)T_*B_*C_*N_];
__device__ __align__(16) float g_vs[(size_t)T_*B_*C_*N_];
__device__ __align__(16) float g_rs[(size_t)T_*B_*C_*N_];
__device__ __align__(16) float g_x1[(size_t)T_*B_*C_*N_];
__device__ __align__(16) float g_h [(size_t)T_*B_*H_*N_];

__device__ __forceinline__ float* buf_ptr(int id){
  switch(id){
    case 0: return g_qs; case 1: return g_ks; case 2: return g_vs;
    case 3: return g_rs; case 4: return g_x1; default: return g_h;
  }
}

// ---------------- packed f32x2 helpers (bit-exact per-lane IEEE fma) -------
__device__ __forceinline__ unsigned long long pk2(float v){
  unsigned long long r; unsigned u = __float_as_uint(v);
  asm("mov.b64 %0, {%1, %1};" : "=l"(r) : "r"(u));
  return r;
}
__device__ __forceinline__ void fma2(unsigned long long &d,
                                     unsigned long long a, unsigned long long b){
  asm("fma.rn.f32x2 %0, %1, %2, %0;" : "+l"(d) : "l"(a), "l"(b));
}
__device__ __forceinline__ float2 unpk(unsigned long long p){
  unsigned lo, hi;
  asm("mov.b64 {%0, %1}, %2;" : "=r"(lo), "=r"(hi) : "l"(p));
  return make_float2(__uint_as_float(lo), __uint_as_float(hi));
}

// ------------- fused GEMM + (reference-order) BN + LIF scan over T
// All T=4 pre-activations accumulated in one k-pass (t in the register tile);
// per-output accumulation: serial ascending-c fp32 fma; FFMA2 pairs ADJACENT
// O-ROWS (b-operand = duplicated X pair) -> bit-exact vs scalar reference.
// Block tile: 128(o) x 32(n) x 4(t), 128 threads, micro 16(o) x 2(n) x 4(t)
// (P=J=8: crossbar-optimal 2.0 B/FFMA2). Double-buffered smem, register-
// prefetch pipeline, COMPILE-TIME stage indices (2 tiles per loop iter).
#define XROW 320   // 16 n-pairs * 20 floats (n-even 8, n-odd 8, pad 4)
__device__ __forceinline__ void gemm_lif_body(
    const float* __restrict__ X, float* __restrict__ out,
    const float* __restrict__ res,
    const float* __restrict__ W, const float* __restrict__ bn,
    const float* __restrict__ bias, int Cin, int Cout,
    int b, int o0, int n0)
{
  __shared__ __align__(16) float sW [2][BK][128];   // [stage][k][o]
  __shared__ __align__(16) float sX2[2][BK][XROW];  // dup pairs [stage][k][col]
  __shared__ float sBN[4][128];                     // s, mean, beta, convbias

  const int tid = threadIdx.x;
  const int to = tid >> 4;          // 0..7  -> o micro group (16 o each)
  const int tn = tid & 15;          // 0..15 -> n pair (2 each)

  // W staging: thread owns o-row tid, 8 k's (2 float4)
  // X staging: xk = k row, xt = t, xq -> n chunks {xq*4, xq*4+16}
  const int xk = tid >> 4;          // 0..7
  const int xt = (tid >> 2) & 3;    // 0..3
  const int xq = tid & 3;           // 0..3

  {
    const int o = o0 + tid;
    sBN[0][tid] = bn[o] / sqrtf(bn[3*Cout + o] + 1e-5f);
    sBN[1][tid] = bn[2*Cout + o];
    sBN[2][tid] = bn[Cout + o];
    sBN[3][tid] = bias ? bias[o] : 0.0f;
  }

  // register prefetch buffers
  float4 rw0, rw1, rx0, rx1;
  auto load_regs = [&](int kk){
    const float* wp = W + (size_t)(o0 + tid) * Cin + kk;
    rw0 = *(const float4*)(wp);
    rw1 = *(const float4*)(wp + 4);
    const float* xp = X + ((size_t)(xt*B_ + b) * Cin + kk + xk) * N_ + n0;
    rx0 = *(const float4*)(xp + xq*4);
    rx1 = *(const float4*)(xp + xq*4 + 16);
  };
  auto sts_regs = [&](int s){
    sW[s][0][tid] = rw0.x; sW[s][1][tid] = rw0.y;
    sW[s][2][tid] = rw0.z; sW[s][3][tid] = rw0.w;
    sW[s][4][tid] = rw1.x; sW[s][5][tid] = rw1.y;
    sW[s][6][tid] = rw1.z; sW[s][7][tid] = rw1.w;
    float xv0[4] = {rx0.x, rx0.y, rx0.z, rx0.w};
    float xv1[4] = {rx1.x, rx1.y, rx1.z, rx1.w};
#pragma unroll
    for (int i=0;i<4;i++){
      const int nl = xq*4 + i;                        // local n 0..15
      const int col = (nl>>1)*20 + (nl&1)*8 + xt*2;
      *(unsigned long long*)&sX2[s][xk][col] = pk2(xv0[i]);
    }
#pragma unroll
    for (int i=0;i<4;i++){
      const int nl = xq*4 + 16 + i;                   // local n 16..31
      const int col = (nl>>1)*20 + (nl&1)*8 + xt*2;
      *(unsigned long long*)&sX2[s][xk][col] = pk2(xv1[i]);
    }
  };

  // accp[p][j]: packed (o = to*16+2p, +1), j = n*4 + t  (n in 0..1, t in 0..3)
  unsigned long long accp[8][8];
#pragma unroll
  for (int i=0;i<8;i++)
#pragma unroll
    for (int j=0;j<8;j++) accp[i][j] = 0ULL;

  auto compute = [&](int s){
#pragma unroll
    for (int k = 0; k < BK; k++){
      const float* wp = &sW[s][k][to*16];
      ulonglong2 w01 = *(const ulonglong2*)(wp);
      ulonglong2 w23 = *(const ulonglong2*)(wp + 4);
      ulonglong2 w45 = *(const ulonglong2*)(wp + 8);
      ulonglong2 w67 = *(const ulonglong2*)(wp + 12);
      unsigned long long ap[8] = {w01.x,w01.y,w23.x,w23.y,
                                  w45.x,w45.y,w67.x,w67.y};
      const float* bp = &sX2[s][k][tn*20];
      ulonglong2 q0 = *(const ulonglong2*)(bp);      // (n0,t0),(n0,t1)
      ulonglong2 q1 = *(const ulonglong2*)(bp + 4);  // (n0,t2),(n0,t3)
      ulonglong2 q2 = *(const ulonglong2*)(bp + 8);  // (n1,t0),(n1,t1)
      ulonglong2 q3 = *(const ulonglong2*)(bp + 12); // (n1,t2),(n1,t3)
      unsigned long long pb[8] = {q0.x,q0.y,q1.x,q1.y,q2.x,q2.y,q3.x,q3.y};
#pragma unroll
      for (int j=0; j<8; j++){    // j outer: pb[j] reused by 8 consecutive FFMA2
#pragma unroll
        for (int p=0; p<8; p++) fma2(accp[p][j], ap[p], pb[j]);
      }
    }
  };

  const int ntile = Cin / BK;     // 32 or 128: always even
  load_regs(0);

#pragma unroll 1
  for (int it = 0; it < ntile; it += 2){
    // ---- stage 0: tile it ----
    sts_regs(0);
    __syncthreads();
    load_regs((it + 1) * BK);     // always valid (ntile even)
    compute(0);
    // ---- stage 1: tile it+1 ----
    sts_regs(1);
    __syncthreads();
    if (it + 2 < ntile) load_regs((it + 2) * BK);
    compute(1);
    // WAR safety: each sts targets the stage whose readers all passed the
    // immediately preceding barrier (one barrier per tile, stages fixed).
  }

  // epilogue: bias -> BN (reference order) -> LIF scan over t -> +residual
#pragma unroll
  for (int p=0; p<8; p++) {
    float accs[2][8];    // [o-lane within pair][j = n*4 + t]
#pragma unroll
    for (int j=0;j<8;j++){
      float2 pr = unpk(accp[p][j]);
      accs[0][j] = pr.x; accs[1][j] = pr.y;
    }
#pragma unroll
    for (int h2=0; h2<2; h2++) {
      const int oloc = to*16 + 2*p + h2;
      const int o = o0 + oloc;
      const float s_  = sBN[0][oloc];
      const float m_  = sBN[1][oloc];
      const float be_ = sBN[2][oloc];
      const float bc_ = sBN[3][oloc];
#pragma unroll
      for (int n=0; n<2; n++) {
        float mem = 0.0f;
        float sp[4];
#pragma unroll
        for (int t=0; t<4; t++) {
          float ypre = accs[h2][n*4 + t] + bc_;            // conv bias (0 if none)
          float y    = fmaf(ypre - m_, s_, be_);           // (y-m)*s + beta
          float m2   = mem + (y - mem) * 0.5f;             // mem + (y-mem)/TAU
          bool fire  = (m2 > 0.5f);                        // spike(mem - 0.5)
          mem = fire ? 0.0f : m2;                          // hard reset
          sp[t] = fire ? 1.0f : 0.0f;
        }
#pragma unroll
        for (int t=0; t<4; t++) {
          const size_t idx = ((size_t)(t*B_ + b) * Cout + o) * N_ + n0 + tn*2 + n;
          float v = sp[t];
          if (res) v += res[idx];
          out[idx] = v;
        }
      }
    }
  }
}

// q,k,v fused: blockIdx.y in [0,6): gemm = gy>>1, o0 = (gy&1)*128
__global__ __launch_bounds__(128, 2)
void qkv_gemm_kernel(const float* __restrict__ x,
                     const float* __restrict__ Wq, const float* __restrict__ bnq,
                     const float* __restrict__ Wk, const float* __restrict__ bnk,
                     const float* __restrict__ Wv, const float* __restrict__ bnv)
{
  const int gy = blockIdx.y;
  const int gemm = gy >> 1;
  const int o0 = (gy & 1) * 128;
  const float* W  = (gemm == 0) ? Wq  : (gemm == 1) ? Wk  : Wv;
  const float* bn = (gemm == 0) ? bnq : (gemm == 1) ? bnk : bnv;
  float* out = buf_ptr(gemm);
  gemm_lif_body(x, out, nullptr, W, bn, nullptr, C_, C_,
                blockIdx.z, o0, blockIdx.x * 32);
}

__global__ __launch_bounds__(128, 2)
void gemm_lif_kernel(const float* __restrict__ Xext, float* __restrict__ outext,
                     const float* __restrict__ resext,
                     int xid, int oid, int rid,
                     const float* __restrict__ W, const float* __restrict__ bn,
                     const float* __restrict__ bias, int Cin, int Cout)
{
  const float* X   = (xid >= 0) ? buf_ptr(xid) : Xext;
  float* out       = (oid >= 0) ? buf_ptr(oid) : outext;
  const float* res = (rid == -2) ? nullptr : ((rid >= 0) ? buf_ptr(rid) : resext);
  gemm_lif_body(X, out, res, W, bn, bias, Cin, Cout,
                blockIdx.z, blockIdx.y * 128, blockIdx.x * 32);
}

// ------------- spiking linear attention + attn-LIF (bit-exact integer math)
// KV[d1][d2] = sum_m k[d1,m]*v[d2,m] via ballot-bitpack + popc (spikes binary)
// r = 0.0625 * q @ KV ; LIF over t (dyadic-exact).
__global__ __launch_bounds__(256)
void attn_lif_kernel()
{
  __shared__ unsigned kb[16][17], vb[16][17];
  __shared__ float sKV[16][17];
  const int b = blockIdx.x;
  const int h = blockIdx.y;
  const int tid = threadIdx.x;
  const int warp = tid >> 5, lane = tid & 31;
  const int d1 = tid >> 4, d2 = tid & 15;

  float mem[2][16];
#pragma unroll
  for (int j=0;j<2;j++)
#pragma unroll
    for (int d=0; d<16; d++) mem[j][d] = 0.0f;

#pragma unroll 1
  for (int t=0; t<T_; t++){
    const size_t base = ((size_t)(t*B_ + b) * C_ + h*16) * N_;
    __syncthreads();   // prior iteration done reading kb/vb/sKV

#pragma unroll 4
    for (int i = 0; i < 32; i++){
      const int idx = warp * 32 + i;          // 0..255
      const int row = idx >> 4, word = idx & 15;
      const size_t off = base + (size_t)row * N_ + word * 32 + lane;
      unsigned uk = __ballot_sync(0xffffffffu, g_ks[off] != 0.0f);
      unsigned uv = __ballot_sync(0xffffffffu, g_vs[off] != 0.0f);
      if (lane == 0){ kb[row][word] = uk; vb[row][word] = uv; }
    }
    __syncthreads();

    {
      int kv = 0;
#pragma unroll
      for (int w=0; w<16; w++) kv += __popc(kb[d1][w] & vb[d2][w]);
      sKV[d1][d2] = (float)kv;
    }
    __syncthreads();

#pragma unroll
    for (int half=0; half<2; half++){
      const int n = tid + half*256;
      float qv[16];
#pragma unroll
      for (int dd=0; dd<16; dd++) qv[dd] = g_qs[base + (size_t)dd*N_ + n];
#pragma unroll
      for (int d=0; d<16; d++){
        float r = 0.0f;
#pragma unroll
        for (int dd=0; dd<16; dd++) r = fmaf(qv[dd], sKV[dd][d], r);
        r *= 0.0625f;
        float m2 = mem[half][d] + (r - mem[half][d]) * 0.5f;
        bool fire = (m2 > 0.5f);
        mem[half][d] = fire ? 0.0f : m2;
        g_rs[base + (size_t)d*N_ + n] = fire ? 1.0f : 0.0f;
      }
    }
  }
}

// --------------------------------------------------------------------------
extern "C" void kernel_launch(void* const* d_in, const int* in_sizes, int n_in,
                              void* d_out, int out_size)
{
  const float* x       = (const float*)d_in[0];
  const float* q_w     = (const float*)d_in[1];
  const float* q_bn    = (const float*)d_in[2];
  const float* k_w     = (const float*)d_in[3];
  const float* k_bn    = (const float*)d_in[4];
  const float* v_w     = (const float*)d_in[5];
  const float* v_bn    = (const float*)d_in[6];
  const float* proj_w  = (const float*)d_in[7];
  const float* proj_bn = (const float*)d_in[8];
  const float* fc1_w   = (const float*)d_in[9];
  const float* fc1_b   = (const float*)d_in[10];
  const float* fc1_bn  = (const float*)d_in[11];
  const float* fc2_w   = (const float*)d_in[12];
  const float* fc2_b   = (const float*)d_in[13];
  const float* fc2_bn  = (const float*)d_in[14];
  float* out = (float*)d_out;

  dim3 blk(128);

  // q, k, v = conv+bn+lif(x) -> binary spikes (one fused launch, t in-register)
  qkv_gemm_kernel<<<dim3(N_/32, 6, B_), blk>>>(x, q_w, q_bn, k_w, k_bn, v_w, v_bn);

  // linear attention (q (kT v)) * 0.0625 + attn-LIF -> g_rs
  attn_lif_kernel<<<dim3(B_, 16), dim3(256)>>>();

  // proj conv+bn+lif, fused residual: x1 = x + spike
  gemm_lif_kernel<<<dim3(N_/32, C_/128, B_), blk>>>(nullptr, nullptr, x, 3, 4, -1,
                                                    proj_w, proj_bn, nullptr, C_, C_);

  // fc1 conv+bn+lif -> g_h (Cout=1024)
  gemm_lif_kernel<<<dim3(N_/32, H_/128, B_), blk>>>(nullptr, nullptr, nullptr, 4, 5, -2,
                                                    fc1_w, fc1_bn, fc1_b, C_, H_);

  // fc2 conv+bn+lif, fused residual: out = x1 + spike (Cin=1024)
  gemm_lif_kernel<<<dim3(N_/32, C_/128, B_), blk>>>(nullptr, out, nullptr, 5, -1, 4,
                                                    fc2_w, fc2_bn, fc2_b, H_, C_);
}